// round 3
// baseline (speedup 1.0000x reference)
#include <cuda_runtime.h>

#define FD 128
#define NMAX 51200   // headroom over N=50000

// Scratch: G = feats @ (W + W^T), plus the symmetrized W itself.
__device__ float g_Ws[FD * FD];
__device__ float g_G[(size_t)NMAX * FD];

// ---------------------------------------------------------------------------
// Kernel 1: build Ws = W + W^T and zero the (poisoned) output.
// ---------------------------------------------------------------------------
__global__ void prep_kernel(const float* __restrict__ W,
                            float* __restrict__ out, int M) {
    int t = blockIdx.x * blockDim.x + threadIdx.x;
    if (t < FD * FD) {
        int r = t >> 7;
        int c = t & 127;
        g_Ws[t] = W[t] + W[c * FD + r];
    }
    if (t < M) out[t] = 0.0f;
}

// ---------------------------------------------------------------------------
// Kernel 2: G = feats @ Ws   (N x 128) @ (128 x 128), fp32.
// Block = 256 threads = 8 warps; each warp computes 8 rows, each lane 4 cols.
// Rows staged in smem (contiguous 32KB block load); Ws read via __ldg
// (64KB, L1-resident, amortized over 8 rows per load).
// ---------------------------------------------------------------------------
__global__ __launch_bounds__(256) void gemm_kernel(const float* __restrict__ feats,
                                                   int N) {
    __shared__ float4 srow[64 * 32];   // 64 rows x 128 floats = 32 KB

    const int base = blockIdx.x * 64;
    const int tid = threadIdx.x;

    // Stage up to 64 contiguous rows of feats into smem.
    int nval = N - base;
    if (nval > 64) nval = 64;
    const float4* src = (const float4*)feats + (size_t)base * 32;
    for (int i = tid; i < nval * 32; i += 256) srow[i] = src[i];
    __syncthreads();

    const int w = tid >> 5;
    const int lane = tid & 31;
    const int r0 = w * 8;
    if (base + r0 >= N) return;

    float4 acc[8];
#pragma unroll
    for (int r = 0; r < 8; r++) acc[r] = make_float4(0.f, 0.f, 0.f, 0.f);

    const float4* Ws4 = (const float4*)g_Ws;   // [k][c4]: index k*32 + c4

#pragma unroll 4
    for (int k4 = 0; k4 < 32; k4++) {
        // Ws rows k = 4*k4 .. 4*k4+3, cols 4*lane .. 4*lane+3
        float4 wv0 = __ldg(&Ws4[(k4 * 4 + 0) * 32 + lane]);
        float4 wv1 = __ldg(&Ws4[(k4 * 4 + 1) * 32 + lane]);
        float4 wv2 = __ldg(&Ws4[(k4 * 4 + 2) * 32 + lane]);
        float4 wv3 = __ldg(&Ws4[(k4 * 4 + 3) * 32 + lane]);
#pragma unroll
        for (int r = 0; r < 8; r++) {
            float4 a = srow[(r0 + r) * 32 + k4];   // broadcast LDS
            acc[r].x = fmaf(a.x, wv0.x, fmaf(a.y, wv1.x, fmaf(a.z, wv2.x, fmaf(a.w, wv3.x, acc[r].x))));
            acc[r].y = fmaf(a.x, wv0.y, fmaf(a.y, wv1.y, fmaf(a.z, wv2.y, fmaf(a.w, wv3.y, acc[r].y))));
            acc[r].z = fmaf(a.x, wv0.z, fmaf(a.y, wv1.z, fmaf(a.z, wv2.z, fmaf(a.w, wv3.z, acc[r].z))));
            acc[r].w = fmaf(a.x, wv0.w, fmaf(a.y, wv1.w, fmaf(a.z, wv2.w, fmaf(a.w, wv3.w, acc[r].w))));
        }
    }

    int nr = N - base - r0;
    if (nr > 8) nr = 8;
    float4* dst = (float4*)g_G + (size_t)(base + r0) * 32;
    for (int r = 0; r < nr; r++) dst[r * 32 + lane] = acc[r];
}

// ---------------------------------------------------------------------------
// Kernel 3: per-edge dot product + segment atomicAdd.
// One warp per edge: lane l loads float4 l of G[i] and feats[j] (coalesced
// 512B rows, L2-resident), shfl-reduces, lane 0 does one REDG per edge.
// NOTE: indices are int32 (JAX without x64 downgrades int64 -> int32).
// ---------------------------------------------------------------------------
__global__ __launch_bounds__(256) void edge_kernel(const float* __restrict__ feats,
                                                   const int* __restrict__ nbr,
                                                   const int* __restrict__ mol,
                                                   float* __restrict__ out, int E) {
    const int e = blockIdx.x * 8 + (threadIdx.x >> 5);
    if (e >= E) return;
    const int lane = threadIdx.x & 31;

    const int i = __ldg(&nbr[e]);             // broadcast within warp
    const int j = __ldg(&nbr[(size_t)E + e]);

    const float4* gi = (const float4*)g_G + (size_t)i * 32;
    const float4* fj = (const float4*)feats + (size_t)j * 32;

    float4 a = __ldg(&gi[lane]);
    float4 b = __ldg(&fj[lane]);
    float s = a.x * b.x + a.y * b.y + a.z * b.z + a.w * b.w;

#pragma unroll
    for (int o = 16; o; o >>= 1) s += __shfl_xor_sync(0xffffffffu, s, o);

    if (lane == 0) {
        atomicAdd(out + __ldg(&mol[e]), s);
    }
}

// ---------------------------------------------------------------------------
// Launch wrapper (graph-capturable: kernel launches only).
// Inputs (metadata order):
//   [0] molec_feature_vectures f32 [N,128]
//   [1] W                      f32 [128,128]
//   [2] mo_neighbour_indices   i32 [2,E]
//   [3] mo_mol_id              i32 [E]
//   [4] n_output               (scalar; ignored — use out_size)
// Output: f32 [M]
// ---------------------------------------------------------------------------
extern "C" void kernel_launch(void* const* d_in, const int* in_sizes, int n_in,
                              void* d_out, int out_size) {
    const float* feats = (const float*)d_in[0];
    const float* W = (const float*)d_in[1];
    const int* nbr = (const int*)d_in[2];
    const int* mol = (const int*)d_in[3];
    float* out = (float*)d_out;

    const int N = in_sizes[0] / FD;
    const int E = in_sizes[2] / 2;
    const int M = out_size;

    int prep_elems = FD * FD;
    if (M > prep_elems) prep_elems = M;
    prep_kernel<<<(prep_elems + 255) / 256, 256>>>(W, out, M);

    gemm_kernel<<<(N + 63) / 64, 256>>>(feats, N);

    edge_kernel<<<(E + 7) / 8, 256>>>(feats, nbr, mol, out, E);
}

// round 5
// speedup vs baseline: 1.2386x; 1.2386x over previous
#include <cuda_runtime.h>
#include <cuda_fp16.h>

#define FD 128
#define NMAX 51200   // headroom over N=50000

// Scratch: Ws = W + W^T (fp32), G = feats @ Ws (fp16), feats copy (fp16).
__device__ float  g_Ws[FD * FD];
__device__ __half g_Gh[(size_t)NMAX * FD];
__device__ __half g_Fh[(size_t)NMAX * FD];

// ---------------------------------------------------------------------------
// Kernel 1: build Ws = W + W^T and zero the (poisoned) output.
// ---------------------------------------------------------------------------
__global__ void prep_kernel(const float* __restrict__ W,
                            float* __restrict__ out, int M) {
    int t = blockIdx.x * blockDim.x + threadIdx.x;
    if (t < FD * FD) {
        int r = t >> 7;
        int c = t & 127;
        g_Ws[t] = W[t] + W[c * FD + r];
    }
    if (t < M) out[t] = 0.0f;
}

// ---------------------------------------------------------------------------
// Kernel 2: G = feats @ Ws, output fp16; also emits fp16 copy of feats.
// Block = 256 threads = 8 warps; each warp computes 8 rows, each lane 4 cols.
// ---------------------------------------------------------------------------
__global__ __launch_bounds__(256) void gemm_kernel(const float* __restrict__ feats,
                                                   int N) {
    __shared__ float4 srow[64 * 32];   // 64 rows x 128 floats = 32 KB

    const int base = blockIdx.x * 64;
    const int tid = threadIdx.x;

    int nval = N - base;
    if (nval > 64) nval = 64;
    const float4* src = (const float4*)feats + (size_t)base * 32;
    for (int i = tid; i < nval * 32; i += 256) srow[i] = src[i];
    __syncthreads();

    // Emit fp16 copy of the staged rows (index i in float4 units == uint2 units).
    uint2* fh_dst = (uint2*)(g_Fh + (size_t)base * FD);
    for (int i = tid; i < nval * 32; i += 256) {
        float4 v = srow[i];
        __half2 h0 = __floats2half2_rn(v.x, v.y);
        __half2 h1 = __floats2half2_rn(v.z, v.w);
        uint2 p;
        p.x = *(unsigned int*)&h0;
        p.y = *(unsigned int*)&h1;
        fh_dst[i] = p;
    }

    const int w = tid >> 5;
    const int lane = tid & 31;
    const int r0 = w * 8;
    if (base + r0 >= N) return;

    float4 acc[8];
#pragma unroll
    for (int r = 0; r < 8; r++) acc[r] = make_float4(0.f, 0.f, 0.f, 0.f);

    const float4* Ws4 = (const float4*)g_Ws;   // [k][c4]: index k*32 + c4

#pragma unroll 4
    for (int k4 = 0; k4 < 32; k4++) {
        float4 wv0 = __ldg(&Ws4[(k4 * 4 + 0) * 32 + lane]);
        float4 wv1 = __ldg(&Ws4[(k4 * 4 + 1) * 32 + lane]);
        float4 wv2 = __ldg(&Ws4[(k4 * 4 + 2) * 32 + lane]);
        float4 wv3 = __ldg(&Ws4[(k4 * 4 + 3) * 32 + lane]);
#pragma unroll
        for (int r = 0; r < 8; r++) {
            float4 a = srow[(r0 + r) * 32 + k4];   // broadcast LDS
            acc[r].x = fmaf(a.x, wv0.x, fmaf(a.y, wv1.x, fmaf(a.z, wv2.x, fmaf(a.w, wv3.x, acc[r].x))));
            acc[r].y = fmaf(a.x, wv0.y, fmaf(a.y, wv1.y, fmaf(a.z, wv2.y, fmaf(a.w, wv3.y, acc[r].y))));
            acc[r].z = fmaf(a.x, wv0.z, fmaf(a.y, wv1.z, fmaf(a.z, wv2.z, fmaf(a.w, wv3.z, acc[r].z))));
            acc[r].w = fmaf(a.x, wv0.w, fmaf(a.y, wv1.w, fmaf(a.z, wv2.w, fmaf(a.w, wv3.w, acc[r].w))));
        }
    }

    int nr = N - base - r0;
    if (nr > 8) nr = 8;
    for (int r = 0; r < nr; r++) {
        __half2 h0 = __floats2half2_rn(acc[r].x, acc[r].y);
        __half2 h1 = __floats2half2_rn(acc[r].z, acc[r].w);
        uint2 p;
        p.x = *(unsigned int*)&h0;
        p.y = *(unsigned int*)&h1;
        ((uint2*)(g_Gh + (size_t)(base + r0 + r) * FD))[lane] = p;
    }
}

// ---------------------------------------------------------------------------
// Kernel 3: per-edge dot product (fp16 rows, fp32 accumulate) + segment REDG.
// One warp per edge: lane l loads 8B (4 halves) of G[i] and feats[j]
// (256B coalesced rows, L2-resident), shfl-reduces, lane 0 atomics.
// ---------------------------------------------------------------------------
__global__ __launch_bounds__(256) void edge_kernel(const int* __restrict__ nbr,
                                                   const int* __restrict__ mol,
                                                   float* __restrict__ out, int E) {
    const int e = blockIdx.x * 8 + (threadIdx.x >> 5);
    if (e >= E) return;
    const int lane = threadIdx.x & 31;

    const int i = __ldg(&nbr[e]);             // broadcast within warp
    const int j = __ldg(&nbr[(size_t)E + e]);

    const uint2* gi = (const uint2*)(g_Gh + (size_t)i * FD);
    const uint2* fj = (const uint2*)(g_Fh + (size_t)j * FD);

    uint2 ga = __ldg(&gi[lane]);
    uint2 fb = __ldg(&fj[lane]);

    float2 a0 = __half22float2(*(__half2*)&ga.x);
    float2 a1 = __half22float2(*(__half2*)&ga.y);
    float2 b0 = __half22float2(*(__half2*)&fb.x);
    float2 b1 = __half22float2(*(__half2*)&fb.y);

    float s = a0.x * b0.x + a0.y * b0.y + a1.x * b1.x + a1.y * b1.y;

#pragma unroll
    for (int o = 16; o; o >>= 1) s += __shfl_xor_sync(0xffffffffu, s, o);

    if (lane == 0) {
        atomicAdd(out + __ldg(&mol[e]), s);
    }
}

// ---------------------------------------------------------------------------
// Launch wrapper (graph-capturable: kernel launches only).
// Inputs (metadata order):
//   [0] molec_feature_vectures f32 [N,128]
//   [1] W                      f32 [128,128]
//   [2] mo_neighbour_indices   i32 [2,E]
//   [3] mo_mol_id              i32 [E]
//   [4] n_output               (scalar; ignored — use out_size)
// Output: f32 [M]
// ---------------------------------------------------------------------------
extern "C" void kernel_launch(void* const* d_in, const int* in_sizes, int n_in,
                              void* d_out, int out_size) {
    const float* feats = (const float*)d_in[0];
    const float* W = (const float*)d_in[1];
    const int* nbr = (const int*)d_in[2];
    const int* mol = (const int*)d_in[3];
    float* out = (float*)d_out;

    const int N = in_sizes[0] / FD;
    const int E = in_sizes[2] / 2;
    const int M = out_size;

    int prep_elems = FD * FD;
    if (M > prep_elems) prep_elems = M;
    prep_kernel<<<(prep_elems + 255) / 256, 256>>>(W, out, M);

    gemm_kernel<<<(N + 63) / 64, 256>>>(feats, N);

    edge_kernel<<<(E + 7) / 8, 256>>>(nbr, mol, out, E);
}

// round 6
// speedup vs baseline: 1.4975x; 1.2091x over previous
#include <cuda_runtime.h>
#include <cuda_fp16.h>

#define FD 128
#define NMAX 51200   // headroom over N=50000

// Scratch: Wh = (W + W^T) fp16, G = feats @ Ws (fp16), feats copy (fp16).
__device__ __half g_Wh[FD * FD];
__device__ __half g_Gh[(size_t)NMAX * FD];
__device__ __half g_Fh[(size_t)NMAX * FD];

// ---------------------------------------------------------------------------
// Kernel 1: build Wh = fp16(W + W^T) and zero the (poisoned) output.
// ---------------------------------------------------------------------------
__global__ void prep_kernel(const float* __restrict__ W,
                            float* __restrict__ out, int M) {
    int t = blockIdx.x * blockDim.x + threadIdx.x;
    if (t < FD * FD) {
        int r = t >> 7;
        int c = t & 127;
        g_Wh[t] = __float2half_rn(W[t] + W[c * FD + r]);
    }
    if (t < M) out[t] = 0.0f;
}

// ---------------------------------------------------------------------------
// XOR swizzle on 16-byte chunks: row-major [row][128 halves], chunk (8 halves)
// index XORed with (row & 7) -> 8 consecutive rows hit distinct bank groups.
// ---------------------------------------------------------------------------
__device__ __forceinline__ int swz_off(int row, int col_halves) {
    int chunk = col_halves >> 3;
    int within = col_halves & 7;
    return row * FD + ((chunk ^ (row & 7)) << 3) + within;
}

// ---------------------------------------------------------------------------
// Kernel 2: G = feats @ Ws via HMMA (m16n8k16 fp16 in / fp32 acc).
// Block = 256 threads = 8 warps. Tile: 64 rows x 128 cols, K=128.
// Warp (mr,nc): rows mr*16..+16, cols nc*64..+64  (mr=warp>>1, nc=warp&1).
// Also emits the fp16 copy of feats (g_Fh) while staging.
// ---------------------------------------------------------------------------
__global__ __launch_bounds__(256) void gemm_mma_kernel(const float* __restrict__ feats,
                                                       int N) {
    __shared__ __half sA[64 * FD];    // 16 KB
    __shared__ __half sB[128 * FD];   // 32 KB  (total 48 KB)

    const int base = blockIdx.x * 64;
    const int tid = threadIdx.x;

    int nval = N - base;
    if (nval > 64) nval = 64;

    // Stage Ws (fp16) -> sB, swizzled.
    {
        const uint2* src = (const uint2*)g_Wh;
        for (int i = tid; i < 128 * 32; i += 256) {
            int row = i >> 5, c4 = i & 31;
            *(uint2*)&sB[swz_off(row, c4 * 4)] = src[i];
        }
    }

    // Stage feats rows -> sA (fp16, swizzled) + write g_Fh. Zero-pad tail rows.
    {
        const float4* src = (const float4*)feats + (size_t)base * 32;
        uint2* fh_dst = (uint2*)(g_Fh + (size_t)base * FD);
        for (int i = tid; i < 64 * 32; i += 256) {
            int row = i >> 5, c4 = i & 31;
            uint2 p = make_uint2(0u, 0u);
            if (row < nval) {
                float4 v = src[i];
                __half2 h0 = __floats2half2_rn(v.x, v.y);
                __half2 h1 = __floats2half2_rn(v.z, v.w);
                p.x = *(unsigned int*)&h0;
                p.y = *(unsigned int*)&h1;
                fh_dst[i] = p;
            }
            *(uint2*)&sA[swz_off(row, c4 * 4)] = p;
        }
    }
    __syncthreads();

    const int warp = tid >> 5;
    const int lane = tid & 31;
    const int mr = warp >> 1;   // 0..3   row-tile (16 rows)
    const int nc = warp & 1;    // 0..1   col-half (64 cols)

    float acc[8][4];
#pragma unroll
    for (int b = 0; b < 8; b++)
#pragma unroll
        for (int q = 0; q < 4; q++) acc[b][q] = 0.0f;

    // Per-lane ldmatrix source rows.
    const int arow = mr * 16 + (lane & 15);
    const int a_kchunk_base = (lane >> 4);            // 0 or 1 (8-half chunk)
    const int krow_lane = (lane & 7) + ((lane >> 3) & 1) * 8;  // 0..15 within k-step
    const int b_nadd = (lane >> 4) * 8;               // n offset 0 or 8

#pragma unroll
    for (int kk = 0; kk < 8; kk++) {
        // A: 16x16 fragment via ldmatrix.x4
        unsigned a0, a1, a2, a3;
        {
            int koff = kk * 16 + a_kchunk_base * 8;
            unsigned addr = (unsigned)__cvta_generic_to_shared(&sA[swz_off(arow, koff)]);
            asm volatile("ldmatrix.sync.aligned.m8n8.x4.shared.b16 {%0,%1,%2,%3}, [%4];"
                         : "=r"(a0), "=r"(a1), "=r"(a2), "=r"(a3) : "r"(addr));
        }
        const int krow = kk * 16 + krow_lane;
#pragma unroll
        for (int nb2 = 0; nb2 < 4; nb2++) {
            // B: k16 x n16 via ldmatrix.x4.trans -> (b0,b1) nblk 2*nb2, (b2,b3) nblk 2*nb2+1
            unsigned b0, b1, b2, b3;
            int ncol = nc * 64 + nb2 * 16 + b_nadd;
            unsigned addr = (unsigned)__cvta_generic_to_shared(&sB[swz_off(krow, ncol)]);
            asm volatile("ldmatrix.sync.aligned.m8n8.x4.trans.shared.b16 {%0,%1,%2,%3}, [%4];"
                         : "=r"(b0), "=r"(b1), "=r"(b2), "=r"(b3) : "r"(addr));
            float* c0 = acc[2 * nb2];
            asm volatile("mma.sync.aligned.m16n8k16.row.col.f32.f16.f16.f32 "
                         "{%0,%1,%2,%3}, {%4,%5,%6,%7}, {%8,%9}, {%0,%1,%2,%3};"
                         : "+f"(c0[0]), "+f"(c0[1]), "+f"(c0[2]), "+f"(c0[3])
                         : "r"(a0), "r"(a1), "r"(a2), "r"(a3), "r"(b0), "r"(b1));
            float* c1 = acc[2 * nb2 + 1];
            asm volatile("mma.sync.aligned.m16n8k16.row.col.f32.f16.f16.f32 "
                         "{%0,%1,%2,%3}, {%4,%5,%6,%7}, {%8,%9}, {%0,%1,%2,%3};"
                         : "+f"(c1[0]), "+f"(c1[1]), "+f"(c1[2]), "+f"(c1[3])
                         : "r"(a0), "r"(a1), "r"(a2), "r"(a3), "r"(b2), "r"(b3));
        }
    }

    // Epilogue: C frag (row=groupID, cols (lane%4)*2+{0,1}) -> fp16 g_Gh.
    const int row0 = mr * 16 + (lane >> 2);
    const int colb = (lane & 3) * 2;
#pragma unroll
    for (int nb = 0; nb < 8; nb++) {
        int col = nc * 64 + nb * 8 + colb;
        if (base + row0 < N) {
            __half2 h = __floats2half2_rn(acc[nb][0], acc[nb][1]);
            *(unsigned int*)&g_Gh[(size_t)(base + row0) * FD + col] = *(unsigned int*)&h;
        }
        if (base + row0 + 8 < N) {
            __half2 h = __floats2half2_rn(acc[nb][2], acc[nb][3]);
            *(unsigned int*)&g_Gh[(size_t)(base + row0 + 8) * FD + col] = *(unsigned int*)&h;
        }
    }
}

// ---------------------------------------------------------------------------
// Kernel 3: 4 edges per warp (MLP=8 row loads in flight), fp16 rows,
// fp32 accumulate, butterfly reduce, 4 REDGs from lanes 0..3.
// ---------------------------------------------------------------------------
__global__ __launch_bounds__(256) void edge_kernel(const int* __restrict__ nbr,
                                                   const int* __restrict__ mol,
                                                   float* __restrict__ out, int E) {
    const int e0 = (blockIdx.x * 8 + (threadIdx.x >> 5)) * 4;
    if (e0 >= E) return;
    const int lane = threadIdx.x & 31;

    if (e0 + 4 <= E) {
        int4 ii = __ldg((const int4*)(nbr + e0));
        int4 jj = __ldg((const int4*)(nbr + (size_t)E + e0));
        int4 mm = __ldg((const int4*)(mol + e0));

        uint2 ga0 = __ldg(&((const uint2*)(g_Gh + (size_t)ii.x * FD))[lane]);
        uint2 ga1 = __ldg(&((const uint2*)(g_Gh + (size_t)ii.y * FD))[lane]);
        uint2 ga2 = __ldg(&((const uint2*)(g_Gh + (size_t)ii.z * FD))[lane]);
        uint2 ga3 = __ldg(&((const uint2*)(g_Gh + (size_t)ii.w * FD))[lane]);
        uint2 fb0 = __ldg(&((const uint2*)(g_Fh + (size_t)jj.x * FD))[lane]);
        uint2 fb1 = __ldg(&((const uint2*)(g_Fh + (size_t)jj.y * FD))[lane]);
        uint2 fb2 = __ldg(&((const uint2*)(g_Fh + (size_t)jj.z * FD))[lane]);
        uint2 fb3 = __ldg(&((const uint2*)(g_Fh + (size_t)jj.w * FD))[lane]);

        float s0, s1, s2, s3;
        {
            float2 a0 = __half22float2(*(__half2*)&ga0.x), a1 = __half22float2(*(__half2*)&ga0.y);
            float2 b0 = __half22float2(*(__half2*)&fb0.x), b1 = __half22float2(*(__half2*)&fb0.y);
            s0 = a0.x * b0.x + a0.y * b0.y + a1.x * b1.x + a1.y * b1.y;
        }
        {
            float2 a0 = __half22float2(*(__half2*)&ga1.x), a1 = __half22float2(*(__half2*)&ga1.y);
            float2 b0 = __half22float2(*(__half2*)&fb1.x), b1 = __half22float2(*(__half2*)&fb1.y);
            s1 = a0.x * b0.x + a0.y * b0.y + a1.x * b1.x + a1.y * b1.y;
        }
        {
            float2 a0 = __half22float2(*(__half2*)&ga2.x), a1 = __half22float2(*(__half2*)&ga2.y);
            float2 b0 = __half22float2(*(__half2*)&fb2.x), b1 = __half22float2(*(__half2*)&fb2.y);
            s2 = a0.x * b0.x + a0.y * b0.y + a1.x * b1.x + a1.y * b1.y;
        }
        {
            float2 a0 = __half22float2(*(__half2*)&ga3.x), a1 = __half22float2(*(__half2*)&ga3.y);
            float2 b0 = __half22float2(*(__half2*)&fb3.x), b1 = __half22float2(*(__half2*)&fb3.y);
            s3 = a0.x * b0.x + a0.y * b0.y + a1.x * b1.x + a1.y * b1.y;
        }

#pragma unroll
        for (int o = 16; o; o >>= 1) {
            s0 += __shfl_xor_sync(0xffffffffu, s0, o);
            s1 += __shfl_xor_sync(0xffffffffu, s1, o);
            s2 += __shfl_xor_sync(0xffffffffu, s2, o);
            s3 += __shfl_xor_sync(0xffffffffu, s3, o);
        }

        if (lane == 0) atomicAdd(out + mm.x, s0);
        else if (lane == 1) atomicAdd(out + mm.y, s1);
        else if (lane == 2) atomicAdd(out + mm.z, s2);
        else if (lane == 3) atomicAdd(out + mm.w, s3);
    } else {
        // Scalar tail (E not divisible by 4).
        for (int e = e0; e < E; e++) {
            int i = __ldg(&nbr[e]);
            int j = __ldg(&nbr[(size_t)E + e]);
            uint2 ga = __ldg(&((const uint2*)(g_Gh + (size_t)i * FD))[lane]);
            uint2 fb = __ldg(&((const uint2*)(g_Fh + (size_t)j * FD))[lane]);
            float2 a0 = __half22float2(*(__half2*)&ga.x), a1 = __half22float2(*(__half2*)&ga.y);
            float2 b0 = __half22float2(*(__half2*)&fb.x), b1 = __half22float2(*(__half2*)&fb.y);
            float s = a0.x * b0.x + a0.y * b0.y + a1.x * b1.x + a1.y * b1.y;
#pragma unroll
            for (int o = 16; o; o >>= 1) s += __shfl_xor_sync(0xffffffffu, s, o);
            if (lane == 0) atomicAdd(out + __ldg(&mol[e]), s);
        }
    }
}

// ---------------------------------------------------------------------------
// Launch wrapper (graph-capturable: kernel launches only).
// Inputs: [0] feats f32 [N,128], [1] W f32 [128,128],
//         [2] nbr i32 [2,E], [3] mol i32 [E], [4] n_output (use out_size)
// Output: f32 [M]
// ---------------------------------------------------------------------------
extern "C" void kernel_launch(void* const* d_in, const int* in_sizes, int n_in,
                              void* d_out, int out_size) {
    const float* feats = (const float*)d_in[0];
    const float* W = (const float*)d_in[1];
    const int* nbr = (const int*)d_in[2];
    const int* mol = (const int*)d_in[3];
    float* out = (float*)d_out;

    const int N = in_sizes[0] / FD;
    const int E = in_sizes[2] / 2;
    const int M = out_size;

    int prep_elems = FD * FD;
    if (M > prep_elems) prep_elems = M;
    prep_kernel<<<(prep_elems + 255) / 256, 256>>>(W, out, M);

    gemm_mma_kernel<<<(N + 63) / 64, 256>>>(feats, N);

    edge_kernel<<<(E + 31) / 32, 256>>>(nbr, mol, out, E);
}